// round 12
// baseline (speedup 1.0000x reference)
#include <cuda_runtime.h>
#include <math.h>
#include <float.h>

#define NN 20000
#define TT 96
#define CC 128
#define DD 32
#define MMF 64
#define PP 12
#define LL 3
// (1/sqrt(tau)) * d^{-1/4} = 2 * 32^{-0.25}
#define FSC 0.84089641525371454303f
#define NR  36    // kv partial ranges
#define KVR 556   // nodes per kv range (36*556 = 20016 >= 20000)
#define NRK 20    // ksum partial ranges

typedef unsigned long long ull;

// ------------- static device scratch (no allocation allowed) -------------
__device__ float g_h   [8*CC*NN];
__device__ float g_skip[8*CC*NN];
__device__ float g_u   [8*CC*NN];
__device__ float g_phiq[8*MMF*NN];
__device__ float g_phik[8*MMF*NN];   // holds (dash - diag) until k_kfinish
__device__ float g_timee[8*DD], g_weeke[8*DD], g_markc[8*DD], g_bp1[8*DD], g_bp2[8*DD];
__device__ float g_kmax [8];
__device__ float g_ksum [8*MMF];
__device__ float g_ksump[8*NRK*MMF];
__device__ float g_kvp  [8*NR*MMF*CC];
__device__ float g_kv   [8*MMF*CC];

// ------------- f32x2 helpers -------------
__device__ __forceinline__ ull fma2(ull a, ull b, ull c) {
    ull d;
    asm("fma.rn.f32x2 %0, %1, %2, %3;" : "=l"(d) : "l"(a), "l"(b), "l"(c));
    return d;
}
__device__ __forceinline__ ull mul2(ull a, ull b) {
    ull d;
    asm("mul.rn.f32x2 %0, %1, %2;" : "=l"(d) : "l"(a), "l"(b));
    return d;
}
__device__ __forceinline__ ull dup2(float x) {
    ull r;
    asm("mov.b64 %0, {%1, %1};" : "=l"(r) : "f"(x));
    return r;
}
__device__ __forceinline__ ull pk2(float a, float b) {
    ull r;
    asm("mov.b64 %0, {%1, %2};" : "=l"(r) : "f"(a), "f"(b));
    return r;
}
__device__ __forceinline__ float2 unpk(ull v) {
    float2 r;
    asm("mov.b64 {%0, %1}, %2;" : "=f"(r.x), "=f"(r.y) : "l"(v));
    return r;
}
__device__ __forceinline__ ull ld2(const float* p) {
    return *(const ull*)p;
}
__device__ __forceinline__ float sigf(float x) {
    float e = __expf(-x);
    return __fdividef(1.0f, 1.0f + e);
}
__device__ __forceinline__ void atomicMaxF(float* addr, float val) {
    int* ai = (int*)addr;
    int old = *ai;
    while (__int_as_float(old) < val) {
        int assumed = old;
        old = atomicCAS(ai, assumed, __float_as_int(val));
        if (old == assumed) break;
    }
}

extern __shared__ float smx[];

// ------------- per-batch constants -------------
__global__ void k_setup(const float* __restrict__ xm,
                        const float* __restrict__ time_tab, const float* __restrict__ week_tab,
                        const float* __restrict__ input_w,  const float* __restrict__ input_b,
                        const float* __restrict__ w1_w, const float* __restrict__ w1_b,
                        const float* __restrict__ w2_w, const float* __restrict__ w2_b)
{
    __shared__ float teS[8][DD], weS[8][DD];
    int tid = threadIdx.x;
    int b = tid >> 5, c = tid & 31;

    float v0 = xm[b*TT*2 + (TT-1)*2 + 0];
    float v1 = xm[b*TT*2 + (TT-1)*2 + 1];
    int tod = (int)(v0 * (float)TT); tod = min(max(tod, 0), TT-1);
    int dow = (int)(v1 * 7.0f);      dow = min(max(dow, 0), 6);
    float te = time_tab[tod*DD + c];
    float we = week_tab[dow*DD + c];
    g_timee[b*DD + c] = te;
    g_weeke[b*DD + c] = we;
    teS[b][c] = te; weS[b][c] = we;

    float acc = input_b[c];
    const float* iw = input_w + c*288;
    for (int t = 0; t < TT; t++) {
        acc = fmaf(xm[b*TT*2 + t*2 + 0], iw[96  + t], acc);
        acc = fmaf(xm[b*TT*2 + t*2 + 1], iw[192 + t], acc);
    }
    g_markc[b*DD + c] = acc;
    __syncthreads();

    float a1 = w1_b[c], a2 = w2_b[c];
    const float* r1 = w1_w + c*96;
    const float* r2 = w2_w + c*96;
    for (int g = 0; g < DD; g++) {
        a1 = fmaf(teS[b][g], r1[32+g], a1);
        a1 = fmaf(weS[b][g], r1[64+g], a1);
        a2 = fmaf(teS[b][g], r2[32+g], a2);
        a2 = fmaf(weS[b][g], r2[64+g], a2);
    }
    g_bp1[b*DD + c] = a1;
    g_bp2[b*DD + c] = a2;
    if (c == 0) g_kmax[b] = -FLT_MAX;
}

// ------------- stage A (f32x2 + dash caching) -------------
#define SA_IWT 0
#define SA_W1  3072
#define SA_W2  4096
#define SA_PR  5120
#define SA_DSH 7168
#define SA_MC  15360
#define SA_B1  15392
#define SA_B2  15424
#define SA_TE  15456
#define SA_WE  15488
#define SA_RED 15520
#define SA_FLOATS 15648

__global__ __launch_bounds__(128) void k_stageA(
    const float* __restrict__ x, const float* __restrict__ node_emb,
    const float* __restrict__ input_w, const float* __restrict__ w1_w,
    const float* __restrict__ w2_w, const float* __restrict__ proj)
{
    float* iwT = smx + SA_IWT;   // [t][c]
    float* w1S = smx + SA_W1;    // [g][d]
    float* w2S = smx + SA_W2;
    float* prS = smx + SA_PR;    // [m][d]
    float* dashS = smx + SA_DSH; // [m][128 threads]

    int tid = threadIdx.x;
    int b = blockIdx.y;

    for (int e = tid; e < TT*DD; e += 128) { int t = e >> 5, c = e & 31; iwT[e] = input_w[c*288 + t]; }
    for (int e = tid; e < DD*DD; e += 128) { int g = e >> 5, d = e & 31; w1S[e] = w1_w[d*96 + g]; w2S[e] = w2_w[d*96 + g]; }
    for (int e = tid; e < MMF*DD; e += 128) prS[e] = proj[e];
    if (tid < DD) {
        smx[SA_MC + tid] = g_markc[b*DD + tid];
        smx[SA_B1 + tid] = g_bp1[b*DD + tid];
        smx[SA_B2 + tid] = g_bp2[b*DD + tid];
        smx[SA_TE + tid] = g_timee[b*DD + tid];
        smx[SA_WE + tid] = g_weeke[b*DD + tid];
    }
    __syncthreads();

    int n = blockIdx.x*128 + tid;
    float km = -FLT_MAX;

    if (n < NN) {
        // ---- x_in (x part), f32x2 over channel pairs, unroll 4 for MLP ----
        ull xa2[16];
        #pragma unroll
        for (int c = 0; c < 16; c++) xa2[c] = 0ull;
        const float* xp = x + (size_t)b*TT*NN + n;
        #pragma unroll 4
        for (int t = 0; t < TT; t++) {
            ull xv2 = dup2(xp[(size_t)t*NN]);
            const float* iwr = iwT + t*32;
            #pragma unroll
            for (int c = 0; c < 16; c++) xa2[c] = fma2(xv2, ld2(iwr + 2*c), xa2[c]);
        }
        float* hp = g_h    + (size_t)b*CC*NN + n;
        float* sp = g_skip + (size_t)b*CC*NN + n;
        #pragma unroll
        for (int c = 0; c < 16; c++) {
            float2 v = unpk(xa2[c]);
            float a = v.x + smx[SA_MC + 2*c];
            float bb2 = v.y + smx[SA_MC + 2*c+1];
            hp[(size_t)(2*c)*NN] = a;   sp[(size_t)(2*c)*NN] = a;
            hp[(size_t)(2*c+1)*NN] = bb2; sp[(size_t)(2*c+1)*NN] = bb2;
        }

        // ---- nv1/nv2 from node embedding, f32x2 over d pairs ----
        ull nv1[16], nv2[16];
        #pragma unroll
        for (int d = 0; d < 16; d++) {
            nv1[d] = ld2(smx + SA_B1 + 2*d);
            nv2[d] = ld2(smx + SA_B2 + 2*d);
        }
        const float* nep = node_emb + n*32;
        #pragma unroll 4
        for (int g = 0; g < 32; g++) {
            float ne = nep[g];
            hp[(size_t)(32+g)*NN] = ne; sp[(size_t)(32+g)*NN] = ne;
            ull ne2 = dup2(ne);
            const float* r1 = w1S + g*32;
            const float* r2 = w2S + g*32;
            #pragma unroll
            for (int d = 0; d < 16; d++) {
                nv1[d] = fma2(ne2, ld2(r1 + 2*d), nv1[d]);
                nv2[d] = fma2(ne2, ld2(r2 + 2*d), nv2[d]);
            }
        }
        #pragma unroll
        for (int c = 0; c < 32; c++) {
            hp[(size_t)(64+c)*NN] = smx[SA_TE + c]; sp[(size_t)(64+c)*NN] = smx[SA_TE + c];
            hp[(size_t)(96+c)*NN] = smx[SA_WE + c]; sp[(size_t)(96+c)*NN] = smx[SA_WE + c];
        }

        // ---- scale + diag ----
        ull fs2 = dup2(FSC);
        ull d1a = 0ull, d2a = 0ull;
        #pragma unroll
        for (int d = 0; d < 16; d++) {
            nv1[d] = mul2(nv1[d], fs2);
            nv2[d] = mul2(nv2[d], fs2);
            d1a = fma2(nv1[d], nv1[d], d1a);
            d2a = fma2(nv2[d], nv2[d], d2a);
        }
        float2 t1 = unpk(d1a), t2 = unpk(d2a);
        float diag1 = 0.5f*(t1.x + t1.y);
        float diag2 = 0.5f*(t2.x + t2.y);

        // ---- phi_q dash: compute once, cache in smem ----
        float qmax = -FLT_MAX;
        for (int m = 0; m < MMF; m++) {
            ull da = 0ull;
            const float* pr = prS + m*32;
            #pragma unroll
            for (int d = 0; d < 16; d++) da = fma2(nv1[d], ld2(pr + 2*d), da);
            float2 dp = unpk(da);
            float dq = dp.x + dp.y;
            dashS[m*128 + tid] = dq;
            qmax = fmaxf(qmax, dq);
        }
        float* qp = g_phiq + (size_t)b*MMF*NN + n;
        float qoff = diag1 + qmax;
        for (int m = 0; m < MMF; m++)
            qp[(size_t)m*NN] = 0.125f * (__expf(dashS[m*128 + tid] - qoff) + 1e-6f);

        // ---- phi_k pre + batch max over dash ----
        float* kp = g_phik + (size_t)b*MMF*NN + n;
        for (int m = 0; m < MMF; m++) {
            ull da = 0ull;
            const float* pr = prS + m*32;
            #pragma unroll
            for (int d = 0; d < 16; d++) da = fma2(nv2[d], ld2(pr + 2*d), da);
            float2 dp = unpk(da);
            float dk = dp.x + dp.y;
            kp[(size_t)m*NN] = dk - diag2;
            km = fmaxf(km, dk);
        }
    }

    float* red = smx + SA_RED;
    red[tid] = km;
    __syncthreads();
    for (int s = 64; s > 0; s >>= 1) {
        if (tid < s) red[tid] = fmaxf(red[tid], red[tid+s]);
        __syncthreads();
    }
    if (tid == 0) atomicMaxF(&g_kmax[b], red[0]);
}

// ------------- finalize phi_k + partial ksum (warp-per-m) -------------
__global__ __launch_bounds__(256) void k_kfinish() {
    int tid = threadIdx.x;
    int w = tid >> 5, lane = tid & 31;
    int r = blockIdx.x, b = blockIdx.y;
    float kmax = g_kmax[b];
    int n0 = r*1000;
    for (int mi = 0; mi < 8; mi++) {
        int m = w*8 + mi;
        float loc = 0.f;
        float* kp = g_phik + (size_t)(b*MMF + m)*NN;
        for (int n = n0 + lane; n < n0 + 1000; n += 32) {
            float v = 0.125f * (__expf(kp[n] - kmax) + 1e-6f);
            kp[n] = v;
            loc += v;
        }
        #pragma unroll
        for (int o = 16; o > 0; o >>= 1) loc += __shfl_xor_sync(0xffffffffu, loc, o);
        if (lane == 0) g_ksump[(b*NRK + r)*MMF + m] = loc;
    }
}

__global__ void k_ksum() {
    int tid = threadIdx.x;          // 512 = 8b x 64m
    int b = tid >> 6, m = tid & 63;
    float s = 0.f;
    for (int r = 0; r < NRK; r++) s += g_ksump[(b*NRK + r)*MMF + m];
    g_ksum[b*MMF + m] = s;
}

// ------------- gate GEMM: u = sigmoid(h Win^T + bi) * (h Wout^T + bo) -------------
// block = 64 nodes x 256 outputs, 512 threads. f32x2 packed over K-PAIRS:
// both operands (wS rows [c][k], hS rows [n][k]) are k-contiguous -> no dup movs.
// Per k-pair iter: 12 LDS.64 + 32 FFMA2 (73% fma issue fraction).
__global__ __launch_bounds__(512, 1) void k_gate(
    const float* __restrict__ in_w,  const float* __restrict__ in_b,
    const float* __restrict__ out_w, const float* __restrict__ out_b, int l)
{
    float* wS = smx;               // 256 rows * pitch 130 (k-major)
    float* hS = smx + 256*130;     // 64 rows (nodes) * pitch 130 (k-major)
    float* bS = hS + 64*130;       // 256

    int tid = threadIdx.x;
    int b = blockIdx.y;
    int n0 = blockIdx.x*64;

    const float* wi_g = in_w  + (size_t)l*CC*CC;
    const float* wo_g = out_w + (size_t)l*CC*CC;
    for (int e = tid; e < 32768; e += 512) {
        int o = e >> 7, k = e & 127;
        wS[o*130 + k] = (o < 128) ? wi_g[o*128 + k] : wo_g[(o-128)*128 + k];
    }
    if (tid < 256) bS[tid] = (tid < 128) ? in_b[l*CC + tid] : out_b[l*CC + tid - 128];
    // h transposed: hS[n_local][k] ; global read coalesced over n
    const float* hg = g_h + (size_t)b*CC*NN;
    for (int e = tid; e < 8192; e += 512) {
        int c = e >> 6, j = e & 63;
        int n = n0 + j;
        hS[j*130 + c] = (n < NN) ? hg[(size_t)c*NN + n] : 0.f;
    }
    __syncthreads();

    int og = tid >> 4;   // 0..31 -> c0 = og*4 (4 in-channels + 4 out-channels)
    int ng = tid & 15;   // nodes n = ng + 16*i, i 0..3
    int c0 = og*4;

    ull aI[4][4], aO[4][4];   // [j][i], packed (even-k, odd-k) partial sums
    #pragma unroll
    for (int j = 0; j < 4; j++)
        #pragma unroll
        for (int i = 0; i < 4; i++) { aI[j][i] = 0ull; aO[j][i] = 0ull; }

    #pragma unroll 4
    for (int kp = 0; kp < 64; kp++) {
        ull h2[4];
        #pragma unroll
        for (int i = 0; i < 4; i++) h2[i] = ld2(&hS[(ng + 16*i)*130 + 2*kp]);
        ull wI[4], wO[4];
        #pragma unroll
        for (int j = 0; j < 4; j++) {
            wI[j] = ld2(&wS[(c0 + j)*130 + 2*kp]);
            wO[j] = ld2(&wS[(128 + c0 + j)*130 + 2*kp]);
        }
        #pragma unroll
        for (int j = 0; j < 4; j++)
            #pragma unroll
            for (int i = 0; i < 4; i++) {
                aI[j][i] = fma2(wI[j], h2[i], aI[j][i]);
                aO[j][i] = fma2(wO[j], h2[i], aO[j][i]);
            }
    }

    float* ug = g_u + (size_t)b*CC*NN;
    #pragma unroll
    for (int j = 0; j < 4; j++) {
        int c = c0 + j;
        float bi = bS[c], bo = bS[128 + c];
        #pragma unroll
        for (int i = 0; i < 4; i++) {
            int n = n0 + ng + 16*i;
            if (n < NN) {
                float2 vi = unpk(aI[j][i]);
                float2 vo = unpk(aO[j][i]);
                float gi = vi.x + vi.y + bi;
                float oo = vo.x + vo.y + bo;
                ug[(size_t)c*NN + n] = sigf(gi) * oo;
            }
        }
    }
}

// ------------- kv partials (f32x2 over node pairs) -------------
__global__ __launch_bounds__(256) void k_kv() {
    __shared__ __align__(16) float phiS[MMF*34];
    __shared__ __align__(16) float uS[CC*34];
    int tid = threadIdx.x;
    int r = blockIdx.x, b = blockIdx.y;
    int cg = tid & 31, mg = tid >> 5;
    int n0 = r*KVR;
    int nend = min(n0 + KVR, NN);

    ull acc[8][4];
    #pragma unroll
    for (int jm = 0; jm < 8; jm++)
        #pragma unroll
        for (int jc = 0; jc < 4; jc++) acc[jm][jc] = 0ull;

    const float* kpb = g_phik + (size_t)b*MMF*NN;
    const float* upb = g_u    + (size_t)b*CC*NN;

    for (int t = 0; t < 18; t++) {
        int base = n0 + t*32;
        __syncthreads();
        for (int e = tid; e < MMF*32; e += 256) {
            int m = e >> 5, nn = e & 31; int n = base + nn;
            phiS[m*34 + nn] = (n < nend) ? kpb[(size_t)m*NN + n] : 0.f;
        }
        for (int e = tid; e < CC*32; e += 256) {
            int c = e >> 5, nn = e & 31; int n = base + nn;
            uS[c*34 + nn] = (n < nend) ? upb[(size_t)c*NN + n] : 0.f;
        }
        __syncthreads();
        #pragma unroll 2
        for (int t2 = 0; t2 < 16; t2++) {
            ull ph[8], uv[4];
            #pragma unroll
            for (int jm = 0; jm < 8; jm++) ph[jm] = ld2(&phiS[(mg*8 + jm)*34 + 2*t2]);
            #pragma unroll
            for (int jc = 0; jc < 4; jc++) uv[jc] = ld2(&uS[(jc*32 + cg)*34 + 2*t2]);
            #pragma unroll
            for (int jm = 0; jm < 8; jm++)
                #pragma unroll
                for (int jc = 0; jc < 4; jc++)
                    acc[jm][jc] = fma2(ph[jm], uv[jc], acc[jm][jc]);
        }
    }

    float* outp = g_kvp + (size_t)(b*NR + r)*MMF*CC;
    #pragma unroll
    for (int jm = 0; jm < 8; jm++)
        #pragma unroll
        for (int jc = 0; jc < 4; jc++) {
            float2 v = unpk(acc[jm][jc]);
            outp[(mg*8 + jm)*CC + jc*32 + cg] = v.x + v.y;
        }
}

__global__ void k_kvred() {
    int idx = blockIdx.x*256 + threadIdx.x;  // < 8*8192
    int b = idx >> 13, rem = idx & 8191;
    float s = 0.f;
    for (int r = 0; r < NR; r++) s += g_kvp[(size_t)(b*NR + r)*8192 + rem];
    g_kv[(size_t)b*8192 + rem] = s;
}

// ------------- pass2: GEMM-structured num/den + residual + LN -------------
#define P2_KV 0
#define P2_PH 8448
#define P2_H  12672
#define P2_KS 20992
#define P2_LG 21056
#define P2_LB 21184
#define P2_FLOATS 21312

__global__ __launch_bounds__(256, 2) void k_pass2(
    const float* __restrict__ ln_g, const float* __restrict__ ln_b, int l)
{
    float* kvS  = smx + P2_KV;
    float* phiS = smx + P2_PH;
    float* hS   = smx + P2_H;
    float* ksS  = smx + P2_KS;
    float* lgS  = smx + P2_LG;
    float* lbS  = smx + P2_LB;

    int tid = threadIdx.x;
    int b = blockIdx.y;
    int n0 = blockIdx.x*64;

    for (int e = tid; e < MMF*CC; e += 256) {
        int m = e >> 7, c = e & 127;
        kvS[c*66 + m] = g_kv[(size_t)b*8192 + m*128 + c];
    }
    const float* qpb = g_phiq + (size_t)b*MMF*NN;
    for (int e = tid; e < MMF*64; e += 256) {
        int m = e >> 6, nn = e & 63; int n = n0 + nn;
        phiS[nn*66 + m] = (n < NN) ? qpb[(size_t)m*NN + n] : 0.f;
    }
    float* hgb = g_h + (size_t)b*CC*NN;
    for (int e = tid; e < CC*64; e += 256) {
        int c = e >> 6, nn = e & 63; int n = n0 + nn;
        hS[c*65 + nn] = (n < NN) ? hgb[(size_t)c*NN + n] : 0.f;
    }
    if (tid < MMF) ksS[tid] = g_ksum[b*MMF + tid];
    if (tid < CC)  { lgS[tid] = ln_g[l*CC + tid]; lbS[tid] = ln_b[l*CC + tid]; }
    __syncthreads();

    int cg = tid & 15;   // c = jj*16 + cg
    int ng = tid >> 4;   // nodes n = ng*4 + i

    ull acc2[8][4], den2[4];
    #pragma unroll
    for (int jj = 0; jj < 8; jj++)
        #pragma unroll
        for (int i = 0; i < 4; i++) acc2[jj][i] = 0ull;
    #pragma unroll
    for (int i = 0; i < 4; i++) den2[i] = 0ull;

    #pragma unroll 2
    for (int mp = 0; mp < 32; mp++) {
        ull ks2 = ld2(&ksS[2*mp]);
        ull ph2[4];
        #pragma unroll
        for (int i = 0; i < 4; i++) ph2[i] = ld2(&phiS[(ng*4 + i)*66 + 2*mp]);
        ull kv2[8];
        #pragma unroll
        for (int jj = 0; jj < 8; jj++) kv2[jj] = ld2(&kvS[(jj*16 + cg)*66 + 2*mp]);
        #pragma unroll
        for (int jj = 0; jj < 8; jj++)
            #pragma unroll
            for (int i = 0; i < 4; i++)
                acc2[jj][i] = fma2(ph2[i], kv2[jj], acc2[jj][i]);
        #pragma unroll
        for (int i = 0; i < 4; i++) den2[i] = fma2(ph2[i], ks2, den2[i]);
    }

    #pragma unroll
    for (int i = 0; i < 4; i++) {
        int nn = ng*4 + i;
        float2 dv = unpk(den2[i]);
        float inv = __fdividef(1.0f, dv.x + dv.y);
        float hv[8];
        float s = 0.f, ss = 0.f;
        #pragma unroll
        for (int jj = 0; jj < 8; jj++) {
            int c = jj*16 + cg;
            float2 nv = unpk(acc2[jj][i]);
            float v = (nv.x + nv.y)*inv + hS[c*65 + nn];
            hv[jj] = v;
            s += v;
            ss = fmaf(v, v, ss);
        }
        #pragma unroll
        for (int o = 8; o > 0; o >>= 1) {
            s  += __shfl_xor_sync(0xffffffffu, s,  o);
            ss += __shfl_xor_sync(0xffffffffu, ss, o);
        }
        float mu  = s * (1.f/128.f);
        float var = ss * (1.f/128.f) - mu*mu;
        float rstd = rsqrtf(var + 1e-5f);
        #pragma unroll
        for (int jj = 0; jj < 8; jj++) {
            int c = jj*16 + cg;
            hS[c*65 + nn] = (hv[jj] - mu)*rstd*lgS[c] + lbS[c];
        }
    }
    __syncthreads();
    for (int e = tid; e < CC*64; e += 256) {
        int c = e >> 6, nn = e & 63; int n = n0 + nn;
        if (n < NN) hgb[(size_t)c*NN + n] = hS[c*65 + nn];
    }
}

// ------------- output regression + transpose (f32x2 over p-pairs) -------------
__global__ __launch_bounds__(256) void k_out(
    const float* __restrict__ reg_w, const float* __restrict__ reg_b, float* __restrict__ out)
{
    __shared__ __align__(16) float rwT[256*PP];   // [c][p]
    __shared__ __align__(16) float rbS[PP];
    int tid = threadIdx.x;
    int b = blockIdx.y;
    for (int e = tid; e < PP*256; e += 256) {
        int p = e >> 8, c = e & 255;
        rwT[c*PP + p] = reg_w[e];
    }
    if (tid < PP) rbS[tid] = reg_b[tid];
    __syncthreads();

    int n = blockIdx.x*256 + tid;
    if (n >= NN) return;

    ull accq[6];
    #pragma unroll
    for (int q = 0; q < 6; q++) accq[q] = pk2(rbS[2*q], rbS[2*q+1]);
    const float* spb = g_skip + (size_t)b*CC*NN + n;
    const float* hpb = g_h    + (size_t)b*CC*NN + n;
    #pragma unroll 4
    for (int c = 0; c < CC; c++) {
        ull sv2 = dup2(spb[(size_t)c*NN]);
        ull hv2 = dup2(hpb[(size_t)c*NN]);
        const float* rs = rwT + c*PP;
        const float* rh = rwT + (128 + c)*PP;
        #pragma unroll
        for (int q = 0; q < 6; q++) {
            accq[q] = fma2(sv2, ld2(rs + 2*q), accq[q]);
            accq[q] = fma2(hv2, ld2(rh + 2*q), accq[q]);
        }
    }
    #pragma unroll
    for (int q = 0; q < 6; q++) {
        float2 v = unpk(accq[q]);
        out[(size_t)(b*PP + 2*q)*NN + n]   = v.x;
        out[(size_t)(b*PP + 2*q+1)*NN + n] = v.y;
    }
}

// ------------- host -------------
extern "C" void kernel_launch(void* const* d_in, const int* in_sizes, int n_in,
                              void* d_out, int out_size)
{
    const float* x        = (const float*)d_in[0];
    const float* xm       = (const float*)d_in[1];
    const float* node_emb = (const float*)d_in[2];
    const float* time_tab = (const float*)d_in[3];
    const float* week_tab = (const float*)d_in[4];
    const float* input_w  = (const float*)d_in[5];
    const float* input_b  = (const float*)d_in[6];
    const float* w1_w     = (const float*)d_in[7];
    const float* w1_b     = (const float*)d_in[8];
    const float* w2_w     = (const float*)d_in[9];
    const float* w2_b     = (const float*)d_in[10];
    const float* in_w     = (const float*)d_in[11];
    const float* in_b     = (const float*)d_in[12];
    const float* out_w    = (const float*)d_in[13];
    const float* out_b    = (const float*)d_in[14];
    const float* ln_g     = (const float*)d_in[15];
    const float* ln_b     = (const float*)d_in[16];
    const float* reg_w    = (const float*)d_in[17];
    const float* reg_b    = (const float*)d_in[18];
    const float* proj     = (const float*)d_in[19];
    float* out = (float*)d_out;

    size_t sa_smem   = (size_t)SA_FLOATS * sizeof(float);
    size_t gate_smem = (size_t)(256*130 + 64*130 + 256)*sizeof(float); // 167,424 B
    size_t p2_smem   = (size_t)P2_FLOATS * sizeof(float);
    cudaFuncSetAttribute(k_stageA, cudaFuncAttributeMaxDynamicSharedMemorySize, (int)sa_smem);
    cudaFuncSetAttribute(k_gate,   cudaFuncAttributeMaxDynamicSharedMemorySize, (int)gate_smem);
    cudaFuncSetAttribute(k_pass2,  cudaFuncAttributeMaxDynamicSharedMemorySize, (int)p2_smem);

    // Order engineered so k_gate occupies the profiled launch slot (#4).
    k_setup<<<1, 256>>>(xm, time_tab, week_tab, input_w, input_b, w1_w, w1_b, w2_w, w2_b);
    k_stageA<<<dim3(157, 8), 128, sa_smem>>>(x, node_emb, input_w, w1_w, w2_w, proj);
    k_kfinish<<<dim3(NRK, 8), 256>>>();
    k_gate<<<dim3(313, 8), 512, gate_smem>>>(in_w, in_b, out_w, out_b, 0);   // layer 0 gate (slot 4)
    k_ksum<<<1, 512>>>();
    k_kv<<<dim3(NR, 8), 256>>>();
    k_kvred<<<256, 256>>>();
    k_pass2<<<dim3(313, 8), 256, p2_smem>>>(ln_g, ln_b, 0);

    for (int l = 1; l < LL; l++) {
        k_gate<<<dim3(313, 8), 512, gate_smem>>>(in_w, in_b, out_w, out_b, l);
        k_kv<<<dim3(NR, 8), 256>>>();
        k_kvred<<<256, 256>>>();
        k_pass2<<<dim3(313, 8), 256, p2_smem>>>(ln_g, ln_b, l);
    }

    k_out<<<dim3(79, 8), 256>>>(reg_w, reg_b, out);
}

// round 14
// speedup vs baseline: 1.1415x; 1.1415x over previous
#include <cuda_runtime.h>
#include <math.h>
#include <float.h>

#define NN 20000
#define TT 96
#define CC 128
#define DD 32
#define MMF 64
#define PP 12
#define LL 3
// (1/sqrt(tau)) * d^{-1/4} = 2 * 32^{-0.25}
#define FSC 0.84089641525371454303f
#define NR  36    // kv partial ranges
#define KVR 556   // nodes per kv range (36*556 = 20016 >= 20000)
#define NRK 20    // ksum partial ranges

typedef unsigned long long ull;

// ------------- static device scratch (no allocation allowed) -------------
__device__ float g_h   [8*CC*NN];
__device__ float g_skip[8*CC*NN];
__device__ float g_u   [8*CC*NN];
__device__ float g_phiq[8*MMF*NN];
__device__ float g_phik[8*MMF*NN];   // holds (dash - diag) until k_kfinish
__device__ float g_timee[8*DD], g_weeke[8*DD], g_markc[8*DD], g_bp1[8*DD], g_bp2[8*DD];
__device__ float g_kmax [8];
__device__ float g_ksum [8*MMF];
__device__ float g_ksump[8*NRK*MMF];
__device__ float g_kvp  [8*NR*MMF*CC];
__device__ float g_kv   [8*MMF*CC];

// ------------- f32x2 helpers -------------
__device__ __forceinline__ ull fma2(ull a, ull b, ull c) {
    ull d;
    asm("fma.rn.f32x2 %0, %1, %2, %3;" : "=l"(d) : "l"(a), "l"(b), "l"(c));
    return d;
}
__device__ __forceinline__ ull mul2(ull a, ull b) {
    ull d;
    asm("mul.rn.f32x2 %0, %1, %2;" : "=l"(d) : "l"(a), "l"(b));
    return d;
}
__device__ __forceinline__ ull dup2(float x) {
    ull r;
    asm("mov.b64 %0, {%1, %1};" : "=l"(r) : "f"(x));
    return r;
}
__device__ __forceinline__ ull pk2(float a, float b) {
    ull r;
    asm("mov.b64 %0, {%1, %2};" : "=l"(r) : "f"(a), "f"(b));
    return r;
}
__device__ __forceinline__ float2 unpk(ull v) {
    float2 r;
    asm("mov.b64 {%0, %1}, %2;" : "=f"(r.x), "=f"(r.y) : "l"(v));
    return r;
}
__device__ __forceinline__ ull ld2(const float* p) {
    return *(const ull*)p;
}
__device__ __forceinline__ float sigf(float x) {
    float e = __expf(-x);
    return __fdividef(1.0f, 1.0f + e);
}
__device__ __forceinline__ void atomicMaxF(float* addr, float val) {
    int* ai = (int*)addr;
    int old = *ai;
    while (__int_as_float(old) < val) {
        int assumed = old;
        old = atomicCAS(ai, assumed, __float_as_int(val));
        if (old == assumed) break;
    }
}

extern __shared__ float smx[];

// ------------- per-batch constants -------------
__global__ void k_setup(const float* __restrict__ xm,
                        const float* __restrict__ time_tab, const float* __restrict__ week_tab,
                        const float* __restrict__ input_w,  const float* __restrict__ input_b,
                        const float* __restrict__ w1_w, const float* __restrict__ w1_b,
                        const float* __restrict__ w2_w, const float* __restrict__ w2_b)
{
    __shared__ float teS[8][DD], weS[8][DD];
    int tid = threadIdx.x;
    int b = tid >> 5, c = tid & 31;

    float v0 = xm[b*TT*2 + (TT-1)*2 + 0];
    float v1 = xm[b*TT*2 + (TT-1)*2 + 1];
    int tod = (int)(v0 * (float)TT); tod = min(max(tod, 0), TT-1);
    int dow = (int)(v1 * 7.0f);      dow = min(max(dow, 0), 6);
    float te = time_tab[tod*DD + c];
    float we = week_tab[dow*DD + c];
    g_timee[b*DD + c] = te;
    g_weeke[b*DD + c] = we;
    teS[b][c] = te; weS[b][c] = we;

    float acc = input_b[c];
    const float* iw = input_w + c*288;
    for (int t = 0; t < TT; t++) {
        acc = fmaf(xm[b*TT*2 + t*2 + 0], iw[96  + t], acc);
        acc = fmaf(xm[b*TT*2 + t*2 + 1], iw[192 + t], acc);
    }
    g_markc[b*DD + c] = acc;
    __syncthreads();

    float a1 = w1_b[c], a2 = w2_b[c];
    const float* r1 = w1_w + c*96;
    const float* r2 = w2_w + c*96;
    for (int g = 0; g < DD; g++) {
        a1 = fmaf(teS[b][g], r1[32+g], a1);
        a1 = fmaf(weS[b][g], r1[64+g], a1);
        a2 = fmaf(teS[b][g], r2[32+g], a2);
        a2 = fmaf(weS[b][g], r2[64+g], a2);
    }
    g_bp1[b*DD + c] = a1;
    g_bp2[b*DD + c] = a2;
    if (c == 0) g_kmax[b] = -FLT_MAX;
}

// ------------- stage A (f32x2 + dash caching) -------------
#define SA_IWT 0
#define SA_W1  3072
#define SA_W2  4096
#define SA_PR  5120
#define SA_DSH 7168
#define SA_MC  15360
#define SA_B1  15392
#define SA_B2  15424
#define SA_TE  15456
#define SA_WE  15488
#define SA_RED 15520
#define SA_FLOATS 15648

__global__ __launch_bounds__(128) void k_stageA(
    const float* __restrict__ x, const float* __restrict__ node_emb,
    const float* __restrict__ input_w, const float* __restrict__ w1_w,
    const float* __restrict__ w2_w, const float* __restrict__ proj)
{
    float* iwT = smx + SA_IWT;   // [t][c]
    float* w1S = smx + SA_W1;    // [g][d]
    float* w2S = smx + SA_W2;
    float* prS = smx + SA_PR;    // [m][d]
    float* dashS = smx + SA_DSH; // [m][128 threads]

    int tid = threadIdx.x;
    int b = blockIdx.y;

    for (int e = tid; e < TT*DD; e += 128) { int t = e >> 5, c = e & 31; iwT[e] = input_w[c*288 + t]; }
    for (int e = tid; e < DD*DD; e += 128) { int g = e >> 5, d = e & 31; w1S[e] = w1_w[d*96 + g]; w2S[e] = w2_w[d*96 + g]; }
    for (int e = tid; e < MMF*DD; e += 128) prS[e] = proj[e];
    if (tid < DD) {
        smx[SA_MC + tid] = g_markc[b*DD + tid];
        smx[SA_B1 + tid] = g_bp1[b*DD + tid];
        smx[SA_B2 + tid] = g_bp2[b*DD + tid];
        smx[SA_TE + tid] = g_timee[b*DD + tid];
        smx[SA_WE + tid] = g_weeke[b*DD + tid];
    }
    __syncthreads();

    int n = blockIdx.x*128 + tid;
    float km = -FLT_MAX;

    if (n < NN) {
        // ---- x_in (x part), f32x2 over channel pairs, unroll 4 for MLP ----
        ull xa2[16];
        #pragma unroll
        for (int c = 0; c < 16; c++) xa2[c] = 0ull;
        const float* xp = x + (size_t)b*TT*NN + n;
        #pragma unroll 4
        for (int t = 0; t < TT; t++) {
            ull xv2 = dup2(xp[(size_t)t*NN]);
            const float* iwr = iwT + t*32;
            #pragma unroll
            for (int c = 0; c < 16; c++) xa2[c] = fma2(xv2, ld2(iwr + 2*c), xa2[c]);
        }
        float* hp = g_h    + (size_t)b*CC*NN + n;
        float* sp = g_skip + (size_t)b*CC*NN + n;
        #pragma unroll
        for (int c = 0; c < 16; c++) {
            float2 v = unpk(xa2[c]);
            float a = v.x + smx[SA_MC + 2*c];
            float bb2 = v.y + smx[SA_MC + 2*c+1];
            hp[(size_t)(2*c)*NN] = a;   sp[(size_t)(2*c)*NN] = a;
            hp[(size_t)(2*c+1)*NN] = bb2; sp[(size_t)(2*c+1)*NN] = bb2;
        }

        // ---- nv1/nv2 from node embedding, f32x2 over d pairs ----
        ull nv1[16], nv2[16];
        #pragma unroll
        for (int d = 0; d < 16; d++) {
            nv1[d] = ld2(smx + SA_B1 + 2*d);
            nv2[d] = ld2(smx + SA_B2 + 2*d);
        }
        const float* nep = node_emb + n*32;
        #pragma unroll 4
        for (int g = 0; g < 32; g++) {
            float ne = nep[g];
            hp[(size_t)(32+g)*NN] = ne; sp[(size_t)(32+g)*NN] = ne;
            ull ne2 = dup2(ne);
            const float* r1 = w1S + g*32;
            const float* r2 = w2S + g*32;
            #pragma unroll
            for (int d = 0; d < 16; d++) {
                nv1[d] = fma2(ne2, ld2(r1 + 2*d), nv1[d]);
                nv2[d] = fma2(ne2, ld2(r2 + 2*d), nv2[d]);
            }
        }
        #pragma unroll
        for (int c = 0; c < 32; c++) {
            hp[(size_t)(64+c)*NN] = smx[SA_TE + c]; sp[(size_t)(64+c)*NN] = smx[SA_TE + c];
            hp[(size_t)(96+c)*NN] = smx[SA_WE + c]; sp[(size_t)(96+c)*NN] = smx[SA_WE + c];
        }

        // ---- scale + diag ----
        ull fs2 = dup2(FSC);
        ull d1a = 0ull, d2a = 0ull;
        #pragma unroll
        for (int d = 0; d < 16; d++) {
            nv1[d] = mul2(nv1[d], fs2);
            nv2[d] = mul2(nv2[d], fs2);
            d1a = fma2(nv1[d], nv1[d], d1a);
            d2a = fma2(nv2[d], nv2[d], d2a);
        }
        float2 t1 = unpk(d1a), t2 = unpk(d2a);
        float diag1 = 0.5f*(t1.x + t1.y);
        float diag2 = 0.5f*(t2.x + t2.y);

        // ---- phi_q dash: compute once, cache in smem ----
        float qmax = -FLT_MAX;
        for (int m = 0; m < MMF; m++) {
            ull da = 0ull;
            const float* pr = prS + m*32;
            #pragma unroll
            for (int d = 0; d < 16; d++) da = fma2(nv1[d], ld2(pr + 2*d), da);
            float2 dp = unpk(da);
            float dq = dp.x + dp.y;
            dashS[m*128 + tid] = dq;
            qmax = fmaxf(qmax, dq);
        }
        float* qp = g_phiq + (size_t)b*MMF*NN + n;
        float qoff = diag1 + qmax;
        for (int m = 0; m < MMF; m++)
            qp[(size_t)m*NN] = 0.125f * (__expf(dashS[m*128 + tid] - qoff) + 1e-6f);

        // ---- phi_k pre + batch max over dash ----
        float* kp = g_phik + (size_t)b*MMF*NN + n;
        for (int m = 0; m < MMF; m++) {
            ull da = 0ull;
            const float* pr = prS + m*32;
            #pragma unroll
            for (int d = 0; d < 16; d++) da = fma2(nv2[d], ld2(pr + 2*d), da);
            float2 dp = unpk(da);
            float dk = dp.x + dp.y;
            kp[(size_t)m*NN] = dk - diag2;
            km = fmaxf(km, dk);
        }
    }

    float* red = smx + SA_RED;
    red[tid] = km;
    __syncthreads();
    for (int s = 64; s > 0; s >>= 1) {
        if (tid < s) red[tid] = fmaxf(red[tid], red[tid+s]);
        __syncthreads();
    }
    if (tid == 0) atomicMaxF(&g_kmax[b], red[0]);
}

// ------------- finalize phi_k + partial ksum (warp-per-m) -------------
__global__ __launch_bounds__(256) void k_kfinish() {
    int tid = threadIdx.x;
    int w = tid >> 5, lane = tid & 31;
    int r = blockIdx.x, b = blockIdx.y;
    float kmax = g_kmax[b];
    int n0 = r*1000;
    for (int mi = 0; mi < 8; mi++) {
        int m = w*8 + mi;
        float loc = 0.f;
        float* kp = g_phik + (size_t)(b*MMF + m)*NN;
        for (int n = n0 + lane; n < n0 + 1000; n += 32) {
            float v = 0.125f * (__expf(kp[n] - kmax) + 1e-6f);
            kp[n] = v;
            loc += v;
        }
        #pragma unroll
        for (int o = 16; o > 0; o >>= 1) loc += __shfl_xor_sync(0xffffffffu, loc, o);
        if (lane == 0) g_ksump[(b*NRK + r)*MMF + m] = loc;
    }
}

__global__ void k_ksum() {
    int tid = threadIdx.x;          // 512 = 8b x 64m
    int b = tid >> 6, m = tid & 63;
    float s = 0.f;
    for (int r = 0; r < NRK; r++) s += g_ksump[(b*NRK + r)*MMF + m];
    g_ksum[b*MMF + m] = s;
}

// ------------- gate GEMM: u = sigmoid(h Win^T + bi) * (h Wout^T + bo) -------------
// block = 128 nodes x 256 outputs, 512 threads. Node-pair f32x2 accumulators.
// Weights stored PRE-DUPLICATED as 8B (w,w) pairs in smem (no dup movs in loop),
// K split into two 64-wide halves to fit smem. Inner iter: 12 LDS.64 + 32 FFMA2.
__global__ __launch_bounds__(512, 1) void k_gate(
    const float* __restrict__ in_w,  const float* __restrict__ in_b,
    const float* __restrict__ out_w, const float* __restrict__ out_b, int l)
{
    ull*   wD = (ull*)smx;             // 256 rows * pitch 65 ull (dup pairs), half-K
    float* hS = smx + 256*65*2;        // 64 k-rows * pitch 130 (128 nodes), half-K
    float* bS = hS + 64*130;           // 256

    int tid = threadIdx.x;
    int b = blockIdx.y;
    int n0 = blockIdx.x*128;

    const float* wi_g = in_w  + (size_t)l*CC*CC;
    const float* wo_g = out_w + (size_t)l*CC*CC;
    const float* hg = g_h + (size_t)b*CC*NN;
    if (tid < 256) bS[tid] = (tid < 128) ? in_b[l*CC + tid] : out_b[l*CC + tid - 128];

    int og = tid >> 4;   // 0..31 -> c0 = og*4
    int ng = tid & 15;   // node pairs np = ng + p*16, p 0..3
    int c0 = og*4;

    ull aI[4][4], aO[4][4];
    #pragma unroll
    for (int j = 0; j < 4; j++)
        #pragma unroll
        for (int p = 0; p < 4; p++) { aI[j][p] = 0ull; aO[j][p] = 0ull; }

    #pragma unroll
    for (int half = 0; half < 2; half++) {
        if (half) __syncthreads();     // previous compute done before refill
        int kbase = half*64;
        // fill duplicated weights: e = o*64 + kk
        for (int e = tid; e < 16384; e += 512) {
            int o = e >> 6, kk = e & 63;
            float w = (o < 128) ? wi_g[o*128 + kbase + kk] : wo_g[(o-128)*128 + kbase + kk];
            wD[o*65 + kk] = dup2(w);
        }
        // fill h tile: e = kk*128 + j
        for (int e = tid; e < 8192; e += 512) {
            int kk = e >> 7, j = e & 127;
            int n = n0 + j;
            hS[kk*130 + j] = (n < NN) ? hg[(size_t)(kbase + kk)*NN + n] : 0.f;
        }
        __syncthreads();

        #pragma unroll 4
        for (int kk = 0; kk < 64; kk++) {
            ull hv2[4];
            #pragma unroll
            for (int p = 0; p < 4; p++) hv2[p] = ld2(&hS[kk*130 + 2*(ng + p*16)]);
            ull wI[4], wO[4];
            #pragma unroll
            for (int j = 0; j < 4; j++) {
                wI[j] = wD[(c0 + j)*65 + kk];
                wO[j] = wD[(128 + c0 + j)*65 + kk];
            }
            #pragma unroll
            for (int j = 0; j < 4; j++)
                #pragma unroll
                for (int p = 0; p < 4; p++) {
                    aI[j][p] = fma2(wI[j], hv2[p], aI[j][p]);
                    aO[j][p] = fma2(wO[j], hv2[p], aO[j][p]);
                }
        }
    }

    float* ug = g_u + (size_t)b*CC*NN;
    #pragma unroll
    for (int j = 0; j < 4; j++) {
        int c = c0 + j;
        float bi = bS[c], bo = bS[128 + c];
        #pragma unroll
        for (int p = 0; p < 4; p++) {
            int n = n0 + 2*(ng + p*16);
            if (n < NN) {
                float2 i2 = unpk(aI[j][p]);
                float2 o2 = unpk(aO[j][p]);
                float2 r;
                r.x = sigf(i2.x + bi) * (o2.x + bo);
                r.y = sigf(i2.y + bi) * (o2.y + bo);
                *(float2*)&ug[(size_t)c*NN + n] = r;
            }
        }
    }
}

// ------------- kv partials (f32x2 over node pairs) -------------
__global__ __launch_bounds__(256) void k_kv() {
    __shared__ __align__(16) float phiS[MMF*34];
    __shared__ __align__(16) float uS[CC*34];
    int tid = threadIdx.x;
    int r = blockIdx.x, b = blockIdx.y;
    int cg = tid & 31, mg = tid >> 5;
    int n0 = r*KVR;
    int nend = min(n0 + KVR, NN);

    ull acc[8][4];
    #pragma unroll
    for (int jm = 0; jm < 8; jm++)
        #pragma unroll
        for (int jc = 0; jc < 4; jc++) acc[jm][jc] = 0ull;

    const float* kpb = g_phik + (size_t)b*MMF*NN;
    const float* upb = g_u    + (size_t)b*CC*NN;

    for (int t = 0; t < 18; t++) {
        int base = n0 + t*32;
        __syncthreads();
        for (int e = tid; e < MMF*32; e += 256) {
            int m = e >> 5, nn = e & 31; int n = base + nn;
            phiS[m*34 + nn] = (n < nend) ? kpb[(size_t)m*NN + n] : 0.f;
        }
        for (int e = tid; e < CC*32; e += 256) {
            int c = e >> 5, nn = e & 31; int n = base + nn;
            uS[c*34 + nn] = (n < nend) ? upb[(size_t)c*NN + n] : 0.f;
        }
        __syncthreads();
        #pragma unroll 2
        for (int t2 = 0; t2 < 16; t2++) {
            ull ph[8], uv[4];
            #pragma unroll
            for (int jm = 0; jm < 8; jm++) ph[jm] = ld2(&phiS[(mg*8 + jm)*34 + 2*t2]);
            #pragma unroll
            for (int jc = 0; jc < 4; jc++) uv[jc] = ld2(&uS[(jc*32 + cg)*34 + 2*t2]);
            #pragma unroll
            for (int jm = 0; jm < 8; jm++)
                #pragma unroll
                for (int jc = 0; jc < 4; jc++)
                    acc[jm][jc] = fma2(ph[jm], uv[jc], acc[jm][jc]);
        }
    }

    float* outp = g_kvp + (size_t)(b*NR + r)*MMF*CC;
    #pragma unroll
    for (int jm = 0; jm < 8; jm++)
        #pragma unroll
        for (int jc = 0; jc < 4; jc++) {
            float2 v = unpk(acc[jm][jc]);
            outp[(mg*8 + jm)*CC + jc*32 + cg] = v.x + v.y;
        }
}

__global__ void k_kvred() {
    int idx = blockIdx.x*256 + threadIdx.x;  // < 8*8192
    int b = idx >> 13, rem = idx & 8191;
    float s = 0.f;
    for (int r = 0; r < NR; r++) s += g_kvp[(size_t)(b*NR + r)*8192 + rem];
    g_kv[(size_t)b*8192 + rem] = s;
}

// ------------- pass2: GEMM-structured num/den + residual + LN -------------
#define P2_KV 0
#define P2_PH 8448
#define P2_H  12672
#define P2_KS 20992
#define P2_LG 21056
#define P2_LB 21184
#define P2_FLOATS 21312

__global__ __launch_bounds__(256, 2) void k_pass2(
    const float* __restrict__ ln_g, const float* __restrict__ ln_b, int l)
{
    float* kvS  = smx + P2_KV;
    float* phiS = smx + P2_PH;
    float* hS   = smx + P2_H;
    float* ksS  = smx + P2_KS;
    float* lgS  = smx + P2_LG;
    float* lbS  = smx + P2_LB;

    int tid = threadIdx.x;
    int b = blockIdx.y;
    int n0 = blockIdx.x*64;

    for (int e = tid; e < MMF*CC; e += 256) {
        int m = e >> 7, c = e & 127;
        kvS[c*66 + m] = g_kv[(size_t)b*8192 + m*128 + c];
    }
    const float* qpb = g_phiq + (size_t)b*MMF*NN;
    for (int e = tid; e < MMF*64; e += 256) {
        int m = e >> 6, nn = e & 63; int n = n0 + nn;
        phiS[nn*66 + m] = (n < NN) ? qpb[(size_t)m*NN + n] : 0.f;
    }
    float* hgb = g_h + (size_t)b*CC*NN;
    for (int e = tid; e < CC*64; e += 256) {
        int c = e >> 6, nn = e & 63; int n = n0 + nn;
        hS[c*65 + nn] = (n < NN) ? hgb[(size_t)c*NN + n] : 0.f;
    }
    if (tid < MMF) ksS[tid] = g_ksum[b*MMF + tid];
    if (tid < CC)  { lgS[tid] = ln_g[l*CC + tid]; lbS[tid] = ln_b[l*CC + tid]; }
    __syncthreads();

    int cg = tid & 15;   // c = jj*16 + cg
    int ng = tid >> 4;   // nodes n = ng*4 + i

    ull acc2[8][4], den2[4];
    #pragma unroll
    for (int jj = 0; jj < 8; jj++)
        #pragma unroll
        for (int i = 0; i < 4; i++) acc2[jj][i] = 0ull;
    #pragma unroll
    for (int i = 0; i < 4; i++) den2[i] = 0ull;

    #pragma unroll 2
    for (int mp = 0; mp < 32; mp++) {
        ull ks2 = ld2(&ksS[2*mp]);
        ull ph2[4];
        #pragma unroll
        for (int i = 0; i < 4; i++) ph2[i] = ld2(&phiS[(ng*4 + i)*66 + 2*mp]);
        ull kv2[8];
        #pragma unroll
        for (int jj = 0; jj < 8; jj++) kv2[jj] = ld2(&kvS[(jj*16 + cg)*66 + 2*mp]);
        #pragma unroll
        for (int jj = 0; jj < 8; jj++)
            #pragma unroll
            for (int i = 0; i < 4; i++)
                acc2[jj][i] = fma2(ph2[i], kv2[jj], acc2[jj][i]);
        #pragma unroll
        for (int i = 0; i < 4; i++) den2[i] = fma2(ph2[i], ks2, den2[i]);
    }

    #pragma unroll
    for (int i = 0; i < 4; i++) {
        int nn = ng*4 + i;
        float2 dv = unpk(den2[i]);
        float inv = __fdividef(1.0f, dv.x + dv.y);
        float hv[8];
        float s = 0.f, ss = 0.f;
        #pragma unroll
        for (int jj = 0; jj < 8; jj++) {
            int c = jj*16 + cg;
            float2 nv = unpk(acc2[jj][i]);
            float v = (nv.x + nv.y)*inv + hS[c*65 + nn];
            hv[jj] = v;
            s += v;
            ss = fmaf(v, v, ss);
        }
        #pragma unroll
        for (int o = 8; o > 0; o >>= 1) {
            s  += __shfl_xor_sync(0xffffffffu, s,  o);
            ss += __shfl_xor_sync(0xffffffffu, ss, o);
        }
        float mu  = s * (1.f/128.f);
        float var = ss * (1.f/128.f) - mu*mu;
        float rstd = rsqrtf(var + 1e-5f);
        #pragma unroll
        for (int jj = 0; jj < 8; jj++) {
            int c = jj*16 + cg;
            hS[c*65 + nn] = (hv[jj] - mu)*rstd*lgS[c] + lbS[c];
        }
    }
    __syncthreads();
    for (int e = tid; e < CC*64; e += 256) {
        int c = e >> 6, nn = e & 63; int n = n0 + nn;
        if (n < NN) hgb[(size_t)c*NN + n] = hS[c*65 + nn];
    }
}

// ------------- output regression + transpose (f32x2 over p-pairs) -------------
__global__ __launch_bounds__(256) void k_out(
    const float* __restrict__ reg_w, const float* __restrict__ reg_b, float* __restrict__ out)
{
    __shared__ __align__(16) float rwT[256*PP];   // [c][p]
    __shared__ __align__(16) float rbS[PP];
    int tid = threadIdx.x;
    int b = blockIdx.y;
    for (int e = tid; e < PP*256; e += 256) {
        int p = e >> 8, c = e & 255;
        rwT[c*PP + p] = reg_w[e];
    }
    if (tid < PP) rbS[tid] = reg_b[tid];
    __syncthreads();

    int n = blockIdx.x*256 + tid;
    if (n >= NN) return;

    ull accq[6];
    #pragma unroll
    for (int q = 0; q < 6; q++) accq[q] = pk2(rbS[2*q], rbS[2*q+1]);
    const float* spb = g_skip + (size_t)b*CC*NN + n;
    const float* hpb = g_h    + (size_t)b*CC*NN + n;
    #pragma unroll 4
    for (int c = 0; c < CC; c++) {
        ull sv2 = dup2(spb[(size_t)c*NN]);
        ull hv2 = dup2(hpb[(size_t)c*NN]);
        const float* rs = rwT + c*PP;
        const float* rh = rwT + (128 + c)*PP;
        #pragma unroll
        for (int q = 0; q < 6; q++) {
            accq[q] = fma2(sv2, ld2(rs + 2*q), accq[q]);
            accq[q] = fma2(hv2, ld2(rh + 2*q), accq[q]);
        }
    }
    #pragma unroll
    for (int q = 0; q < 6; q++) {
        float2 v = unpk(accq[q]);
        out[(size_t)(b*PP + 2*q)*NN + n]   = v.x;
        out[(size_t)(b*PP + 2*q+1)*NN + n] = v.y;
    }
}

// ------------- host -------------
extern "C" void kernel_launch(void* const* d_in, const int* in_sizes, int n_in,
                              void* d_out, int out_size)
{
    const float* x        = (const float*)d_in[0];
    const float* xm       = (const float*)d_in[1];
    const float* node_emb = (const float*)d_in[2];
    const float* time_tab = (const float*)d_in[3];
    const float* week_tab = (const float*)d_in[4];
    const float* input_w  = (const float*)d_in[5];
    const float* input_b  = (const float*)d_in[6];
    const float* w1_w     = (const float*)d_in[7];
    const float* w1_b     = (const float*)d_in[8];
    const float* w2_w     = (const float*)d_in[9];
    const float* w2_b     = (const float*)d_in[10];
    const float* in_w     = (const float*)d_in[11];
    const float* in_b     = (const float*)d_in[12];
    const float* out_w    = (const float*)d_in[13];
    const float* out_b    = (const float*)d_in[14];
    const float* ln_g     = (const float*)d_in[15];
    const float* ln_b     = (const float*)d_in[16];
    const float* reg_w    = (const float*)d_in[17];
    const float* reg_b    = (const float*)d_in[18];
    const float* proj     = (const float*)d_in[19];
    float* out = (float*)d_out;

    size_t sa_smem   = (size_t)SA_FLOATS * sizeof(float);
    size_t gate_smem = (size_t)(256*65*2 + 64*130 + 256)*sizeof(float); // 167,424 B
    size_t p2_smem   = (size_t)P2_FLOATS * sizeof(float);
    cudaFuncSetAttribute(k_stageA, cudaFuncAttributeMaxDynamicSharedMemorySize, (int)sa_smem);
    cudaFuncSetAttribute(k_gate,   cudaFuncAttributeMaxDynamicSharedMemorySize, (int)gate_smem);
    cudaFuncSetAttribute(k_pass2,  cudaFuncAttributeMaxDynamicSharedMemorySize, (int)p2_smem);

    // Order engineered so k_gate occupies the profiled launch slot (#4).
    k_setup<<<1, 256>>>(xm, time_tab, week_tab, input_w, input_b, w1_w, w1_b, w2_w, w2_b);
    k_stageA<<<dim3(157, 8), 128, sa_smem>>>(x, node_emb, input_w, w1_w, w2_w, proj);
    k_kfinish<<<dim3(NRK, 8), 256>>>();
    k_gate<<<dim3(157, 8), 512, gate_smem>>>(in_w, in_b, out_w, out_b, 0);   // layer 0 gate (slot 4)
    k_ksum<<<1, 512>>>();
    k_kv<<<dim3(NR, 8), 256>>>();
    k_kvred<<<256, 256>>>();
    k_pass2<<<dim3(313, 8), 256, p2_smem>>>(ln_g, ln_b, 0);

    for (int l = 1; l < LL; l++) {
        k_gate<<<dim3(157, 8), 512, gate_smem>>>(in_w, in_b, out_w, out_b, l);
        k_kv<<<dim3(NR, 8), 256>>>();
        k_kvred<<<256, 256>>>();
        k_pass2<<<dim3(313, 8), 256, p2_smem>>>(ln_g, ln_b, l);
    }

    k_out<<<dim3(79, 8), 256>>>(reg_w, reg_b, out);
}